// round 15
// baseline (speedup 1.0000x reference)
#include <cuda_runtime.h>
#include <cuda_fp16.h>
#include <mma.h>
#include <math.h>
#include <stdint.h>

using namespace nvcuda;

// ---------------- problem constants ----------------
#define Bz   2048
#define Tz   71
#define Dz   1024
#define Hz   8
#define DHz  128
#define Lz   12
#define NTOK (Bz*Tz)            // 145408
#define MTILES (NTOK/128)       // 1136

// ---------------- device scratch ----------------
__device__ float  g_x  [NTOK*Dz];   // fp32 residual stream
__device__ __half g_xh [NTOK*Dz];   // half mirror (GEMM A operand)
__device__ __half g_qh [NTOK*Dz];
__device__ __half g_kh [NTOK*Dz];
__device__ __half g_vh [NTOK*Dz];
__device__ __half g_y1h[NTOK*Dz];   // lrelu(ff1) half
__device__ __half g_th [Bz*2*Dz];
__device__ float  g_h1 [Bz*2*Dz];
__device__ __half g_qkvTh[Lz*3*Hz*DHz*DHz];
__device__ __half g_ff1Th[Lz*Hz*DHz*Dz];
__device__ __half g_ff2Th[Lz*Hz*DHz*DHz];
__device__ __half g_w1h[2*Dz*2*Dz];

__device__ __forceinline__ float lrelu(float x) { return x > 0.f ? x : 0.2f * x; }

// ---------------- cp.async helpers ----------------
__device__ __forceinline__ void cpa16(uint32_t s, const void* g) {
    asm volatile("cp.async.cg.shared.global [%0], [%1], 16;" :: "r"(s), "l"(g));
}
#define CPA_COMMIT() asm volatile("cp.async.commit_group;" ::: "memory")
#define CPA_WAIT1()  asm volatile("cp.async.wait_group 1;" ::: "memory")
#define CPA_WAIT0()  asm volatile("cp.async.wait_group 0;" ::: "memory")

// ---------------- wmma types ----------------
using FragA  = wmma::fragment<wmma::matrix_a, 16, 16, 16, __half, wmma::row_major>;
using FragB  = wmma::fragment<wmma::matrix_b, 16, 16, 16, __half, wmma::col_major>;
using FragBR = wmma::fragment<wmma::matrix_b, 16, 16, 16, __half, wmma::row_major>;
using FragC  = wmma::fragment<wmma::accumulator, 16, 16, 16, float>;

#define LDSH  72
#define MBUFH (128 * LDSH)
#define GSMH  (2 * 2 * MBUFH * 2)    // 73728 bytes: 2-stage pipeline (proven)
#define STGLD 132                    // fp32 staging stride

// A: row-major [128 x K] half, B: K-contiguous [128n x K] half => C = A @ B^T
// 2-stage cp.async double buffer (round-7 configuration).
__device__ __forceinline__ void gemm_h(const __half* __restrict__ A, int lda,
                                       const __half* __restrict__ B, int ldb,
                                       int K, FragC (&acc)[2][4], __half* sm)
{
    const int tid = threadIdx.x;
    const int warp = tid >> 5;
    const int wm = warp & 3;
    const int wn = warp >> 2;
    const uint32_t smu = (uint32_t)__cvta_generic_to_shared(sm);

#pragma unroll
    for (int i = 0; i < 2; ++i)
#pragma unroll
        for (int j = 0; j < 4; ++j)
            wmma::fill_fragment(acc[i][j], 0.f);

    const int nch = K / 64;

    auto issue = [&](int c, int buf) {
        const int kk = c * 64;
        const uint32_t base = smu + (uint32_t)buf * (2u * MBUFH * 2u);
#pragma unroll
        for (int it = 0; it < 4; ++it) {
            int idx = tid + it * 256;
            int row = idx >> 3, seg = idx & 7;
            cpa16(base + (uint32_t)(row * LDSH * 2 + seg * 16),
                  A + (size_t)row * lda + kk + seg * 8);
        }
#pragma unroll
        for (int it = 0; it < 4; ++it) {
            int idx = tid + it * 256;
            int row = idx >> 3, seg = idx & 7;
            cpa16(base + (uint32_t)(MBUFH * 2) + (uint32_t)(row * LDSH * 2 + seg * 16),
                  B + (size_t)row * ldb + kk + seg * 8);
        }
        CPA_COMMIT();
    };

    issue(0, 0);
    for (int c = 0; c < nch; ++c) {
        if (c + 1 < nch) { issue(c + 1, (c + 1) & 1); CPA_WAIT1(); }
        else             { CPA_WAIT0(); }
        __syncthreads();
        __half* As = sm + (c & 1) * 2 * MBUFH;
        __half* Bs = As + MBUFH;
#pragma unroll
        for (int ks = 0; ks < 4; ++ks) {
            FragA af[2];
            wmma::load_matrix_sync(af[0], As + (wm * 32) * LDSH + ks * 16, LDSH);
            wmma::load_matrix_sync(af[1], As + (wm * 32 + 16) * LDSH + ks * 16, LDSH);
#pragma unroll
            for (int j = 0; j < 4; ++j) {
                FragB bf;
                wmma::load_matrix_sync(bf, Bs + (wn * 64 + j * 16) * LDSH + ks * 16, LDSH);
                wmma::mma_sync(acc[0][j], af[0], bf, acc[0][j]);
                wmma::mma_sync(acc[1][j], af[1], bf, acc[1][j]);
            }
        }
        __syncthreads();
    }
}

// stage 8 acc frags to fp32 smem (stride STGLD); trailing sync
__device__ __forceinline__ void stage_acc(FragC (&acc)[2][4], float* stage) {
    int wm = (threadIdx.x >> 5) & 3, wn = threadIdx.x >> 7;
#pragma unroll
    for (int i = 0; i < 2; ++i)
#pragma unroll
        for (int j = 0; j < 4; ++j)
            wmma::store_matrix_sync(stage + (wm * 32 + i * 16) * STGLD + wn * 64 + j * 16,
                                    acc[i][j], STGLD, wmma::mem_row_major);
    __syncthreads();
}

__device__ __forceinline__ uint4 f8_to_h8(float4 a, float4 b, bool relu) {
    if (relu) {
        a.x = lrelu(a.x); a.y = lrelu(a.y); a.z = lrelu(a.z); a.w = lrelu(a.w);
        b.x = lrelu(b.x); b.y = lrelu(b.y); b.z = lrelu(b.z); b.w = lrelu(b.w);
    }
    __half2 h0 = __floats2half2_rn(a.x, a.y), h1 = __floats2half2_rn(a.z, a.w);
    __half2 h2 = __floats2half2_rn(b.x, b.y), h3 = __floats2half2_rn(b.z, b.w);
    return make_uint4(*(uint32_t*)&h0, *(uint32_t*)&h1, *(uint32_t*)&h2, *(uint32_t*)&h3);
}

// ---------------- GEMM kernels ----------------
__global__ void __launch_bounds__(256, 2) qkv_tc(const __half* __restrict__ qkvT_l)
{
    extern __shared__ __align__(128) __half smh[];
    int sh = blockIdx.x, s = sh >> 3, h = sh & 7;
    int m0 = blockIdx.y * 128;
    FragC acc[2][4];
    gemm_h(g_xh + (size_t)m0 * Dz + h * DHz, Dz,
           qkvT_l + (size_t)sh * (DHz * DHz), DHz, DHz, acc, smh);

    float* stage = (float*)smh;
    stage_acc(acc, stage);
    __half* out = (s == 0) ? g_qh : (s == 1) ? g_kh : g_vh;
#pragma unroll
    for (int it = 0; it < 8; ++it) {
        int idx = threadIdx.x + it * 256;
        int row = idx >> 4, sg = idx & 15;
        float4 a = *(float4*)(stage + row * STGLD + sg * 8);
        float4 b = *(float4*)(stage + row * STGLD + sg * 8 + 4);
        *(uint4*)(out + (size_t)(m0 + row) * Dz + h * DHz + sg * 8) = f8_to_h8(a, b, false);
    }
}

__global__ void __launch_bounds__(256, 2) ff1_tc(const __half* __restrict__ ff1T_l)
{
    extern __shared__ __align__(128) __half smh[];
    int n0 = blockIdx.x * 128, m0 = blockIdx.y * 128;
    FragC acc[2][4];
    gemm_h(g_xh + (size_t)m0 * Dz, Dz,
           ff1T_l + (size_t)n0 * Dz, Dz, Dz, acc, smh);

    float* stage = (float*)smh;
    stage_acc(acc, stage);
#pragma unroll
    for (int it = 0; it < 8; ++it) {
        int idx = threadIdx.x + it * 256;
        int row = idx >> 4, sg = idx & 15;
        float4 a = *(float4*)(stage + row * STGLD + sg * 8);
        float4 b = *(float4*)(stage + row * STGLD + sg * 8 + 4);
        *(uint4*)(g_y1h + (size_t)(m0 + row) * Dz + n0 + sg * 8) = f8_to_h8(a, b, true);
    }
}

// last != 0: skip the g_xh half-mirror write (dead after the final layer)
__global__ void __launch_bounds__(256, 2) ff2_tc(const __half* __restrict__ ff2T_l, int last)
{
    extern __shared__ __align__(128) __half smh[];
    int h = blockIdx.x, m0 = blockIdx.y * 128;
    FragC acc[2][4];
    gemm_h(g_y1h + (size_t)m0 * Dz + h * DHz, Dz,
           ff2T_l + (size_t)h * (DHz * DHz), DHz, DHz, acc, smh);

    int wm = (threadIdx.x >> 5) & 3, wn = threadIdx.x >> 7;
    float* stage = (float*)smh;
#pragma unroll
    for (int i = 0; i < 2; ++i)
#pragma unroll
        for (int j = 0; j < 4; ++j) {
            size_t off = (size_t)(m0 + wm * 32 + i * 16) * Dz + h * DHz + wn * 64 + j * 16;
            FragC c;
            wmma::load_matrix_sync(c, g_x + off, Dz, wmma::mem_row_major);
#pragma unroll
            for (int e = 0; e < c.num_elements; ++e)
                c.x[e] += lrelu(acc[i][j].x[e]);
            wmma::store_matrix_sync(g_x + off, c, Dz, wmma::mem_row_major);
            if (!last)
                wmma::store_matrix_sync(stage + (wm * 32 + i * 16) * STGLD + wn * 64 + j * 16,
                                        c, STGLD, wmma::mem_row_major);
        }
    if (!last) {
        __syncthreads();
#pragma unroll
        for (int it = 0; it < 8; ++it) {
            int idx = threadIdx.x + it * 256;
            int row = idx >> 4, sg = idx & 15;
            float4 a = *(float4*)(stage + row * STGLD + sg * 8);
            float4 b = *(float4*)(stage + row * STGLD + sg * 8 + 4);
            *(uint4*)(g_xh + (size_t)(m0 + row) * Dz + h * DHz + sg * 8) = f8_to_h8(a, b, false);
        }
    }
}

__global__ void __launch_bounds__(256, 2) head_tc(const float* __restrict__ b1)
{
    extern __shared__ __align__(128) __half smh[];
    int n0 = blockIdx.x * 128, m0 = blockIdx.y * 128;
    FragC acc[2][4];
    gemm_h(g_th + (size_t)m0 * 2048, 2048,
           g_w1h + (size_t)n0 * 2048, 2048, 2048, acc, smh);

    float* stage = (float*)smh;
    stage_acc(acc, stage);
#pragma unroll
    for (int it = 0; it < 16; ++it) {
        int idx = threadIdx.x + it * 256;
        int row = idx >> 5, sg = idx & 31;
        float4 a = *(float4*)(stage + row * STGLD + sg * 4);
        int col = n0 + sg * 4;
        a.x = lrelu(a.x + b1[col]);     a.y = lrelu(a.y + b1[col + 1]);
        a.z = lrelu(a.z + b1[col + 2]); a.w = lrelu(a.w + b1[col + 3]);
        *(float4*)(g_h1 + (size_t)(m0 + row) * 2048 + col) = a;
    }
}

// ---------------- attention via wmma fp16 ----------------
#define ALD 136
#define SLD 84
#define PLD 88
#define OLD 132
#define ATTN_SMEM2 (3*80*ALD*2 + 80*SLD*4 + 80*PLD*2)   // 106240

__global__ void __launch_bounds__(256, 2) attn_wmma()
{
    extern __shared__ __align__(16) char smc[];
    __half* ks = (__half*)smc;
    __half* vs = ks + 80 * ALD;
    __half* qs = vs + 80 * ALD;
    float*  S  = (float*)(qs + 80 * ALD);
    __half* P  = (__half*)(S + 80 * SLD);
    float*  Ost = (float*)(smc + 2 * 80 * ALD * 2);

    int b = blockIdx.x, h = blockIdx.y;
    int tid = threadIdx.x, warp = tid >> 5, lane = tid & 31;

    const __half* qb = g_qh + ((size_t)b * Tz) * Dz + h * DHz;
    const __half* kb = g_kh + ((size_t)b * Tz) * Dz + h * DHz;
    const __half* vb = g_vh + ((size_t)b * Tz) * Dz + h * DHz;

    for (int idx = tid; idx < Tz * 16; idx += 256) {
        int t = idx >> 4, sg = idx & 15;
        *(uint4*)(qs + t * ALD + sg * 8) = *(const uint4*)(qb + (size_t)t * Dz + sg * 8);
        *(uint4*)(ks + t * ALD + sg * 8) = *(const uint4*)(kb + (size_t)t * Dz + sg * 8);
        *(uint4*)(vs + t * ALD + sg * 8) = *(const uint4*)(vb + (size_t)t * Dz + sg * 8);
    }
    // Only V pad rows must be zero (P pad cols are 0; 0*NaN would poison O).
    // q/k pad rows feed S rows/cols >= 71 which are never read.
    uint4 z4 = make_uint4(0, 0, 0, 0);
    for (int idx = tid; idx < 9 * 16; idx += 256) {
        int t = 71 + (idx >> 4), sg = idx & 15;
        *(uint4*)(vs + t * ALD + sg * 8) = z4;
    }
    __syncthreads();

    for (int t = warp; t < 25; t += 8) {
        int mi = t / 5, nj = t % 5;
        FragC acc;
        wmma::fill_fragment(acc, 0.f);
#pragma unroll
        for (int k = 0; k < 8; ++k) {
            FragA a; FragB bf;
            wmma::load_matrix_sync(a,  qs + mi * 16 * ALD + k * 16, ALD);
            wmma::load_matrix_sync(bf, ks + nj * 16 * ALD + k * 16, ALD);
            wmma::mma_sync(acc, a, bf, acc);
        }
        wmma::store_matrix_sync(S + mi * 16 * SLD + nj * 16, acc, SLD, wmma::mem_row_major);
    }
    __syncthreads();

    const float inv_scale = 0.08838834764831845f;
    for (int r = warp; r < Tz; r += 8) {
        float mx = -1e30f;
        for (int j = lane; j < Tz; j += 32) mx = fmaxf(mx, S[r * SLD + j] * inv_scale);
#pragma unroll
        for (int o = 16; o; o >>= 1) mx = fmaxf(mx, __shfl_xor_sync(0xffffffffu, mx, o));
        float sum = 0.f;
        for (int j = lane; j < Tz; j += 32) {
            float e = __expf(S[r * SLD + j] * inv_scale - mx);
            S[r * SLD + j] = e;
            sum += e;
        }
#pragma unroll
        for (int o = 16; o; o >>= 1) sum += __shfl_xor_sync(0xffffffffu, sum, o);
        float inv = 1.f / sum;
        for (int j = lane; j < 80; j += 32)
            P[r * PLD + j] = __float2half(j < Tz ? S[r * SLD + j] * inv : 0.f);
    }
    for (int idx = tid; idx < 9 * PLD; idx += 256)
        P[(Tz + idx / PLD) * PLD + (idx % PLD)] = __float2half(0.f);
    __syncthreads();

    FragBR bfr[5];
#pragma unroll
    for (int k = 0; k < 5; ++k)
        wmma::load_matrix_sync(bfr[k], vs + k * 16 * ALD + warp * 16, ALD);
#pragma unroll
    for (int m = 0; m < 5; ++m) {
        FragC acc;
        wmma::fill_fragment(acc, 0.f);
#pragma unroll
        for (int k = 0; k < 5; ++k) {
            FragA a;
            wmma::load_matrix_sync(a, P + m * 16 * PLD + k * 16, PLD);
            wmma::mma_sync(acc, a, bfr[k], acc);
        }
        wmma::store_matrix_sync(Ost + m * 16 * OLD + warp * 16, acc, OLD, wmma::mem_row_major);
    }
    __syncthreads();

    float*  xb  = g_x  + ((size_t)b * Tz) * Dz + h * DHz;
    __half* xhb = g_xh + ((size_t)b * Tz) * Dz + h * DHz;
    for (int idx = tid; idx < Tz * 32; idx += 256) {
        int r = idx >> 5, sg = idx & 31;
        float4 o = *(float4*)(Ost + r * OLD + sg * 4);
        float4 x = *(float4*)(xb + (size_t)r * Dz + sg * 4);
        x.x += o.x; x.y += o.y; x.z += o.z; x.w += o.w;
        *(float4*)(xb + (size_t)r * Dz + sg * 4) = x;
        __half2 h0 = __floats2half2_rn(x.x, x.y), h1 = __floats2half2_rn(x.z, x.w);
        uint2 u = make_uint2(*(uint32_t*)&h0, *(uint32_t*)&h1);
        *(uint2*)(xhb + (size_t)r * Dz + sg * 4) = u;
    }
}

// ---------------- embedding + layernorm (2 tokens per CTA) ----------------
__global__ void __launch_bounds__(256) embed_kernel(
    const int* __restrict__ fen, const int* __restrict__ move,
    const float* __restrict__ rank_emb, const float* __restrict__ file_emb,
    const float* __restrict__ fen_emb, const float* __restrict__ move_emb,
    const float* __restrict__ lng, const float* __restrict__ lnb,
    const float* __restrict__ abs_emb)
{
    __shared__ float buf[16];
    int warp = threadIdx.x >> 5, lane = threadIdx.x & 31;
    int half = warp >> 2;                    // 0/1: which token this warpgroup handles
    int token = blockIdx.x * 2 + half;
    int wtid = (warp & 3) * 32 + lane;       // 0..127 within token group
    int b = token / Tz, t = token - b * Tz;
    float vals[8];

    if (t < 64) {
        int i1 = fen[b * 133 + t];
        int i2 = fen[b * 133 + 64 + t];
        int r = t >> 3, f = t & 7;
#pragma unroll
        for (int c = 0; c < 8; ++c) {
            int d = wtid + c * 128;
            vals[c] = 0.5f * (fen_emb[i1 * Dz + d] + fen_emb[i2 * Dz + d]
                              + rank_emb[r * Dz + d] + file_emb[f * Dz + d])
                      + abs_emb[t * Dz + d];
        }
    } else if (t < 69) {
        int i1 = fen[b * 133 + 128 + (t - 64)];
#pragma unroll
        for (int c = 0; c < 8; ++c) {
            int d = wtid + c * 128;
            vals[c] = fen_emb[i1 * Dz + d] + abs_emb[t * Dz + d];
        }
    } else {
        int i = t - 69;
        int m = move[b * 2 + i];
        int r = m >> 3, f = m & 7;
#pragma unroll
        for (int c = 0; c < 8; ++c) {
            int d = wtid + c * 128;
            vals[c] = (rank_emb[r * Dz + d] + file_emb[f * Dz + d] + move_emb[i * Dz + d]) * 0.58f
                      + abs_emb[t * Dz + d];
        }
    }

    float s1 = 0.f, s2 = 0.f;
#pragma unroll
    for (int c = 0; c < 8; ++c) { s1 += vals[c]; s2 += vals[c] * vals[c]; }
#pragma unroll
    for (int o = 16; o; o >>= 1) {
        s1 += __shfl_xor_sync(0xffffffffu, s1, o);
        s2 += __shfl_xor_sync(0xffffffffu, s2, o);
    }
    if (lane == 0) { buf[warp] = s1; buf[8 + warp] = s2; }
    __syncthreads();
    float t1 = 0.f, t2 = 0.f;
#pragma unroll
    for (int w = 0; w < 4; ++w) {
        t1 += buf[half * 4 + w];
        t2 += buf[8 + half * 4 + w];
    }
    float mean = t1 * (1.f / 1024.f);
    float var  = t2 * (1.f / 1024.f) - mean * mean;
    float inv  = rsqrtf(var + 1e-5f);

    float*  xp  = g_x  + (size_t)token * Dz;
    __half* xhp = g_xh + (size_t)token * Dz;
#pragma unroll
    for (int c = 0; c < 8; ++c) {
        int d = wtid + c * 128;
        float y = (vals[c] - mean) * inv * lng[d] + lnb[d];
        xp[d]  = y;
        xhp[d] = __float2half(y);
    }
}

// ---------------- weight prep ----------------
__global__ void transposeW(const float* __restrict__ src, __half* __restrict__ dst, int K)
{
    __shared__ float tile[32][33];
    size_t mstride = (size_t)K * 128;
    src += blockIdx.z * mstride;
    dst += blockIdx.z * mstride;
    int k0 = blockIdx.x * 32, n0 = blockIdx.y * 32;
    for (int i = threadIdx.y; i < 32; i += 8)
        tile[i][threadIdx.x] = src[(size_t)(k0 + i) * 128 + n0 + threadIdx.x];
    __syncthreads();
    for (int i = threadIdx.y; i < 32; i += 8)
        dst[(size_t)(n0 + i) * K + k0 + threadIdx.x] = __float2half(tile[threadIdx.x][i]);
}

__global__ void __launch_bounds__(512) halfW1(const float* __restrict__ W1)
{
    int idx = blockIdx.x * 512 + threadIdx.x;
    g_w1h[idx] = __float2half(W1[idx]);
}

// ---------------- head: gather + LN over 2048 ----------------
__device__ __forceinline__ void blockReduce2(float& s1, float& s2) {
    __shared__ float buf[32];
    int lane = threadIdx.x & 31, warp = threadIdx.x >> 5;
#pragma unroll
    for (int o = 16; o; o >>= 1) {
        s1 += __shfl_xor_sync(0xffffffffu, s1, o);
        s2 += __shfl_xor_sync(0xffffffffu, s2, o);
    }
    if (lane == 0) { buf[warp] = s1; buf[16 + warp] = s2; }
    __syncthreads();
    float t1 = 0.f, t2 = 0.f;
#pragma unroll
    for (int w = 0; w < 8; ++w) { t1 += buf[w]; t2 += buf[16 + w]; }
    s1 = t1; s2 = t2;
}

__global__ void __launch_bounds__(256) gather_ln_kernel(const float* __restrict__ g,
                                                        const float* __restrict__ bb)
{
    int b = blockIdx.x, tid = threadIdx.x;
    const float* x69 = g_x + ((size_t)b * Tz + 69) * Dz;
    float vals[8];
#pragma unroll
    for (int c = 0; c < 8; ++c) vals[c] = x69[tid + c * 256];
    float s1 = 0.f, s2 = 0.f;
#pragma unroll
    for (int c = 0; c < 8; ++c) { s1 += vals[c]; s2 += vals[c] * vals[c]; }
    blockReduce2(s1, s2);
    float mean = s1 * (1.f / 2048.f);
    float var  = s2 * (1.f / 2048.f) - mean * mean;
    float inv  = rsqrtf(var + 1e-5f);
    __half* tp = g_th + (size_t)b * 2048;
#pragma unroll
    for (int c = 0; c < 8; ++c) {
        int k = tid + c * 256;
        tp[k] = __float2half((vals[c] - mean) * inv * g[k] + bb[k]);
    }
}

__global__ void __launch_bounds__(256) final_kernel(const float* __restrict__ W2,
                                                    const float* __restrict__ b2,
                                                    float* __restrict__ out)
{
    int b = blockIdx.x, tid = threadIdx.x;
    const float* hp = g_h1 + (size_t)b * 2048;
    float s = 0.f;
    for (int k = tid; k < 2048; k += 256) s = fmaf(hp[k], W2[k], s);
    float dummy = 0.f;
    blockReduce2(s, dummy);
    if (tid == 0) out[b] = 1.f / (1.f + __expf(-(s + b2[0])));
}

// ---------------- launch ----------------
extern "C" void kernel_launch(void* const* d_in, const int* in_sizes, int n_in,
                              void* d_out, int out_size)
{
    const int*   fen      = (const int*)  d_in[0];
    const int*   move     = (const int*)  d_in[1];
    const float* rank_emb = (const float*)d_in[2];
    const float* file_emb = (const float*)d_in[3];
    const float* fen_emb  = (const float*)d_in[4];
    const float* move_emb = (const float*)d_in[5];
    const float* ln_emb_g = (const float*)d_in[6];
    const float* ln_emb_b = (const float*)d_in[7];
    const float* abs_emb  = (const float*)d_in[8];
    const float* qkvw     = (const float*)d_in[9];
    const float* ff1w     = (const float*)d_in[10];
    const float* ff2w     = (const float*)d_in[11];
    const float* ln_out_g = (const float*)d_in[12];
    const float* ln_out_b = (const float*)d_in[13];
    const float* W1       = (const float*)d_in[14];
    const float* b1       = (const float*)d_in[15];
    const float* W2       = (const float*)d_in[16];
    const float* b2       = (const float*)d_in[17];
    float* out = (float*)d_out;

    cudaFuncSetAttribute(attn_wmma, cudaFuncAttributeMaxDynamicSharedMemorySize, ATTN_SMEM2);
    cudaFuncSetAttribute(qkv_tc,  cudaFuncAttributeMaxDynamicSharedMemorySize, GSMH);
    cudaFuncSetAttribute(ff1_tc,  cudaFuncAttributeMaxDynamicSharedMemorySize, GSMH);
    cudaFuncSetAttribute(ff2_tc,  cudaFuncAttributeMaxDynamicSharedMemorySize, GSMH);
    cudaFuncSetAttribute(head_tc, cudaFuncAttributeMaxDynamicSharedMemorySize, GSMH);

    __half* qkvT; cudaGetSymbolAddress((void**)&qkvT, g_qkvTh);
    __half* ff1T; cudaGetSymbolAddress((void**)&ff1T, g_ff1Th);
    __half* ff2T; cudaGetSymbolAddress((void**)&ff2T, g_ff2Th);
    transposeW<<<dim3(4, 4, Lz * 3 * Hz), dim3(32, 8)>>>(qkvw, qkvT, 128);
    transposeW<<<dim3(32, 4, Lz * Hz), dim3(32, 8)>>>(ff1w, ff1T, 1024);
    transposeW<<<dim3(4, 4, Lz * Hz), dim3(32, 8)>>>(ff2w, ff2T, 128);
    halfW1<<<(2 * Dz * 2 * Dz) / 512, 512>>>(W1);

    embed_kernel<<<NTOK / 2, 256>>>(fen, move, rank_emb, file_emb, fen_emb, move_emb,
                                    ln_emb_g, ln_emb_b, abs_emb);

    for (int l = 0; l < Lz; ++l) {
        const __half* qkvT_l = qkvT + (size_t)l * 3 * Hz * DHz * DHz;
        const __half* ff1T_l = ff1T + (size_t)l * Hz * DHz * Dz;
        const __half* ff2T_l = ff2T + (size_t)l * Hz * DHz * DHz;
        qkv_tc<<<dim3(24, MTILES), 256, GSMH>>>(qkvT_l);
        attn_wmma<<<dim3(Bz, Hz), 256, ATTN_SMEM2>>>();
        ff1_tc<<<dim3(8, MTILES), 256, GSMH>>>(ff1T_l);
        ff2_tc<<<dim3(8, MTILES), 256, GSMH>>>(ff2T_l, l == Lz - 1 ? 1 : 0);
    }

    gather_ln_kernel<<<Bz, 256>>>(ln_out_g, ln_out_b);
    head_tc<<<dim3(16, 16), 256, GSMH>>>(b1);
    final_kernel<<<Bz, 256>>>(W2, b2, out);
}

// round 16
// speedup vs baseline: 1.0041x; 1.0041x over previous
#include <cuda_runtime.h>
#include <cuda_fp16.h>
#include <mma.h>
#include <math.h>
#include <stdint.h>

using namespace nvcuda;

// ---------------- problem constants ----------------
#define Bz   2048
#define Tz   71
#define Dz   1024
#define Hz   8
#define DHz  128
#define Lz   12
#define NTOK (Bz*Tz)            // 145408
#define MTILES (NTOK/128)       // 1136

// ---------------- device scratch ----------------
__device__ float  g_x  [NTOK*Dz];   // fp32 residual stream
__device__ __half g_xh [NTOK*Dz];   // half mirror (GEMM A operand)
__device__ __half g_qh [NTOK*Dz];
__device__ __half g_kh [NTOK*Dz];
__device__ __half g_vh [NTOK*Dz];
__device__ __half g_y1h[NTOK*Dz];   // lrelu(ff1) half
__device__ __half g_th [Bz*2*Dz];
__device__ float  g_h1 [Bz*2*Dz];
__device__ __half g_qkvTh[Lz*3*Hz*DHz*DHz];
__device__ __half g_ff1Th[Lz*Hz*DHz*Dz];
__device__ __half g_ff2Th[Lz*Hz*DHz*DHz];
__device__ __half g_w1h[2*Dz*2*Dz];

__device__ __forceinline__ float lrelu(float x) { return x > 0.f ? x : 0.2f * x; }

// ---------------- cp.async helpers ----------------
__device__ __forceinline__ void cpa16(uint32_t s, const void* g) {
    asm volatile("cp.async.cg.shared.global [%0], [%1], 16;" :: "r"(s), "l"(g));
}
#define CPA_COMMIT() asm volatile("cp.async.commit_group;" ::: "memory")
#define CPA_WAIT1()  asm volatile("cp.async.wait_group 1;" ::: "memory")
#define CPA_WAIT0()  asm volatile("cp.async.wait_group 0;" ::: "memory")

// ---------------- wmma types ----------------
using FragA  = wmma::fragment<wmma::matrix_a, 16, 16, 16, __half, wmma::row_major>;
using FragB  = wmma::fragment<wmma::matrix_b, 16, 16, 16, __half, wmma::col_major>;
using FragBR = wmma::fragment<wmma::matrix_b, 16, 16, 16, __half, wmma::row_major>;
using FragC  = wmma::fragment<wmma::accumulator, 16, 16, 16, float>;

#define LDSH  72
#define MBUFH (128 * LDSH)
#define GSMH  (2 * 2 * MBUFH * 2)    // 73728 bytes: 2-stage pipeline (proven)
#define STGLD 132                    // fp32 staging stride

// A: row-major [128 x K] half, B: K-contiguous [128n x K] half => C = A @ B^T
// 2-stage cp.async double buffer (round-7 configuration).
__device__ __forceinline__ void gemm_h(const __half* __restrict__ A, int lda,
                                       const __half* __restrict__ B, int ldb,
                                       int K, FragC (&acc)[2][4], __half* sm)
{
    const int tid = threadIdx.x;
    const int warp = tid >> 5;
    const int wm = warp & 3;
    const int wn = warp >> 2;
    const uint32_t smu = (uint32_t)__cvta_generic_to_shared(sm);

#pragma unroll
    for (int i = 0; i < 2; ++i)
#pragma unroll
        for (int j = 0; j < 4; ++j)
            wmma::fill_fragment(acc[i][j], 0.f);

    const int nch = K / 64;

    auto issue = [&](int c, int buf) {
        const int kk = c * 64;
        const uint32_t base = smu + (uint32_t)buf * (2u * MBUFH * 2u);
#pragma unroll
        for (int it = 0; it < 4; ++it) {
            int idx = tid + it * 256;
            int row = idx >> 3, seg = idx & 7;
            cpa16(base + (uint32_t)(row * LDSH * 2 + seg * 16),
                  A + (size_t)row * lda + kk + seg * 8);
        }
#pragma unroll
        for (int it = 0; it < 4; ++it) {
            int idx = tid + it * 256;
            int row = idx >> 3, seg = idx & 7;
            cpa16(base + (uint32_t)(MBUFH * 2) + (uint32_t)(row * LDSH * 2 + seg * 16),
                  B + (size_t)row * ldb + kk + seg * 8);
        }
        CPA_COMMIT();
    };

    issue(0, 0);
    for (int c = 0; c < nch; ++c) {
        if (c + 1 < nch) { issue(c + 1, (c + 1) & 1); CPA_WAIT1(); }
        else             { CPA_WAIT0(); }
        __syncthreads();
        __half* As = sm + (c & 1) * 2 * MBUFH;
        __half* Bs = As + MBUFH;
#pragma unroll
        for (int ks = 0; ks < 4; ++ks) {
            FragA af[2];
            wmma::load_matrix_sync(af[0], As + (wm * 32) * LDSH + ks * 16, LDSH);
            wmma::load_matrix_sync(af[1], As + (wm * 32 + 16) * LDSH + ks * 16, LDSH);
#pragma unroll
            for (int j = 0; j < 4; ++j) {
                FragB bf;
                wmma::load_matrix_sync(bf, Bs + (wn * 64 + j * 16) * LDSH + ks * 16, LDSH);
                wmma::mma_sync(acc[0][j], af[0], bf, acc[0][j]);
                wmma::mma_sync(acc[1][j], af[1], bf, acc[1][j]);
            }
        }
        __syncthreads();
    }
}

// stage 8 acc frags to fp32 smem (stride STGLD); trailing sync
__device__ __forceinline__ void stage_acc(FragC (&acc)[2][4], float* stage) {
    int wm = (threadIdx.x >> 5) & 3, wn = threadIdx.x >> 7;
#pragma unroll
    for (int i = 0; i < 2; ++i)
#pragma unroll
        for (int j = 0; j < 4; ++j)
            wmma::store_matrix_sync(stage + (wm * 32 + i * 16) * STGLD + wn * 64 + j * 16,
                                    acc[i][j], STGLD, wmma::mem_row_major);
    __syncthreads();
}

__device__ __forceinline__ uint4 f8_to_h8(float4 a, float4 b, bool relu) {
    if (relu) {
        a.x = lrelu(a.x); a.y = lrelu(a.y); a.z = lrelu(a.z); a.w = lrelu(a.w);
        b.x = lrelu(b.x); b.y = lrelu(b.y); b.z = lrelu(b.z); b.w = lrelu(b.w);
    }
    __half2 h0 = __floats2half2_rn(a.x, a.y), h1 = __floats2half2_rn(a.z, a.w);
    __half2 h2 = __floats2half2_rn(b.x, b.y), h3 = __floats2half2_rn(b.z, b.w);
    return make_uint4(*(uint32_t*)&h0, *(uint32_t*)&h1, *(uint32_t*)&h2, *(uint32_t*)&h3);
}

// ---------------- GEMM kernels ----------------
__global__ void __launch_bounds__(256, 2) qkv_tc(const __half* __restrict__ qkvT_l)
{
    extern __shared__ __align__(128) __half smh[];
    int sh = blockIdx.x, s = sh >> 3, h = sh & 7;
    int m0 = blockIdx.y * 128;
    FragC acc[2][4];
    gemm_h(g_xh + (size_t)m0 * Dz + h * DHz, Dz,
           qkvT_l + (size_t)sh * (DHz * DHz), DHz, DHz, acc, smh);

    float* stage = (float*)smh;
    stage_acc(acc, stage);
    __half* out = (s == 0) ? g_qh : (s == 1) ? g_kh : g_vh;
#pragma unroll
    for (int it = 0; it < 8; ++it) {
        int idx = threadIdx.x + it * 256;
        int row = idx >> 4, sg = idx & 15;
        float4 a = *(float4*)(stage + row * STGLD + sg * 8);
        float4 b = *(float4*)(stage + row * STGLD + sg * 8 + 4);
        *(uint4*)(out + (size_t)(m0 + row) * Dz + h * DHz + sg * 8) = f8_to_h8(a, b, false);
    }
}

__global__ void __launch_bounds__(256, 2) ff1_tc(const __half* __restrict__ ff1T_l)
{
    extern __shared__ __align__(128) __half smh[];
    int n0 = blockIdx.x * 128, m0 = blockIdx.y * 128;
    FragC acc[2][4];
    gemm_h(g_xh + (size_t)m0 * Dz, Dz,
           ff1T_l + (size_t)n0 * Dz, Dz, Dz, acc, smh);

    float* stage = (float*)smh;
    stage_acc(acc, stage);
#pragma unroll
    for (int it = 0; it < 8; ++it) {
        int idx = threadIdx.x + it * 256;
        int row = idx >> 4, sg = idx & 15;
        float4 a = *(float4*)(stage + row * STGLD + sg * 8);
        float4 b = *(float4*)(stage + row * STGLD + sg * 8 + 4);
        *(uint4*)(g_y1h + (size_t)(m0 + row) * Dz + n0 + sg * 8) = f8_to_h8(a, b, true);
    }
}

__global__ void __launch_bounds__(256, 2) ff2_tc(const __half* __restrict__ ff2T_l)
{
    extern __shared__ __align__(128) __half smh[];
    int h = blockIdx.x, m0 = blockIdx.y * 128;
    FragC acc[2][4];
    gemm_h(g_y1h + (size_t)m0 * Dz + h * DHz, Dz,
           ff2T_l + (size_t)h * (DHz * DHz), DHz, DHz, acc, smh);

    int wm = (threadIdx.x >> 5) & 3, wn = threadIdx.x >> 7;
    float* stage = (float*)smh;
#pragma unroll
    for (int i = 0; i < 2; ++i)
#pragma unroll
        for (int j = 0; j < 4; ++j) {
            size_t off = (size_t)(m0 + wm * 32 + i * 16) * Dz + h * DHz + wn * 64 + j * 16;
            FragC c;
            wmma::load_matrix_sync(c, g_x + off, Dz, wmma::mem_row_major);
#pragma unroll
            for (int e = 0; e < c.num_elements; ++e)
                c.x[e] += lrelu(acc[i][j].x[e]);
            wmma::store_matrix_sync(g_x + off, c, Dz, wmma::mem_row_major);
            wmma::store_matrix_sync(stage + (wm * 32 + i * 16) * STGLD + wn * 64 + j * 16,
                                    c, STGLD, wmma::mem_row_major);
        }
    __syncthreads();
#pragma unroll
    for (int it = 0; it < 8; ++it) {
        int idx = threadIdx.x + it * 256;
        int row = idx >> 4, sg = idx & 15;
        float4 a = *(float4*)(stage + row * STGLD + sg * 8);
        float4 b = *(float4*)(stage + row * STGLD + sg * 8 + 4);
        *(uint4*)(g_xh + (size_t)(m0 + row) * Dz + h * DHz + sg * 8) = f8_to_h8(a, b, false);
    }
}

__global__ void __launch_bounds__(256, 2) head_tc(const float* __restrict__ b1)
{
    extern __shared__ __align__(128) __half smh[];
    int n0 = blockIdx.x * 128, m0 = blockIdx.y * 128;
    FragC acc[2][4];
    gemm_h(g_th + (size_t)m0 * 2048, 2048,
           g_w1h + (size_t)n0 * 2048, 2048, 2048, acc, smh);

    float* stage = (float*)smh;
    stage_acc(acc, stage);
#pragma unroll
    for (int it = 0; it < 16; ++it) {
        int idx = threadIdx.x + it * 256;
        int row = idx >> 5, sg = idx & 31;
        float4 a = *(float4*)(stage + row * STGLD + sg * 4);
        int col = n0 + sg * 4;
        a.x = lrelu(a.x + b1[col]);     a.y = lrelu(a.y + b1[col + 1]);
        a.z = lrelu(a.z + b1[col + 2]); a.w = lrelu(a.w + b1[col + 3]);
        *(float4*)(g_h1 + (size_t)(m0 + row) * 2048 + col) = a;
    }
}

// ---------------- attention via wmma fp16 ----------------
#define ALD 136
#define SLD 84
#define PLD 88
#define OLD 132
#define ATTN_SMEM2 (3*80*ALD*2 + 80*SLD*4 + 80*PLD*2)   // 106240

__global__ void __launch_bounds__(256, 2) attn_wmma()
{
    extern __shared__ __align__(16) char smc[];
    __half* ks = (__half*)smc;
    __half* vs = ks + 80 * ALD;
    __half* qs = vs + 80 * ALD;
    float*  S  = (float*)(qs + 80 * ALD);
    __half* P  = (__half*)(S + 80 * SLD);
    float*  Ost = (float*)(smc + 2 * 80 * ALD * 2);

    int b = blockIdx.x, h = blockIdx.y;
    int tid = threadIdx.x, warp = tid >> 5, lane = tid & 31;

    const __half* qb = g_qh + ((size_t)b * Tz) * Dz + h * DHz;
    const __half* kb = g_kh + ((size_t)b * Tz) * Dz + h * DHz;
    const __half* vb = g_vh + ((size_t)b * Tz) * Dz + h * DHz;

    for (int idx = tid; idx < Tz * 16; idx += 256) {
        int t = idx >> 4, sg = idx & 15;
        *(uint4*)(qs + t * ALD + sg * 8) = *(const uint4*)(qb + (size_t)t * Dz + sg * 8);
        *(uint4*)(ks + t * ALD + sg * 8) = *(const uint4*)(kb + (size_t)t * Dz + sg * 8);
        *(uint4*)(vs + t * ALD + sg * 8) = *(const uint4*)(vb + (size_t)t * Dz + sg * 8);
    }
    // Only V pad rows must be zero (P pad cols are 0; 0*NaN would poison O).
    // q/k pad rows feed S rows/cols >= 71 which are never read.
    uint4 z4 = make_uint4(0, 0, 0, 0);
    for (int idx = tid; idx < 9 * 16; idx += 256) {
        int t = 71 + (idx >> 4), sg = idx & 15;
        *(uint4*)(vs + t * ALD + sg * 8) = z4;
    }
    __syncthreads();

    for (int t = warp; t < 25; t += 8) {
        int mi = t / 5, nj = t % 5;
        FragC acc;
        wmma::fill_fragment(acc, 0.f);
#pragma unroll
        for (int k = 0; k < 8; ++k) {
            FragA a; FragB bf;
            wmma::load_matrix_sync(a,  qs + mi * 16 * ALD + k * 16, ALD);
            wmma::load_matrix_sync(bf, ks + nj * 16 * ALD + k * 16, ALD);
            wmma::mma_sync(acc, a, bf, acc);
        }
        wmma::store_matrix_sync(S + mi * 16 * SLD + nj * 16, acc, SLD, wmma::mem_row_major);
    }
    __syncthreads();

    const float inv_scale = 0.08838834764831845f;
    for (int r = warp; r < Tz; r += 8) {
        float mx = -1e30f;
        for (int j = lane; j < Tz; j += 32) mx = fmaxf(mx, S[r * SLD + j] * inv_scale);
#pragma unroll
        for (int o = 16; o; o >>= 1) mx = fmaxf(mx, __shfl_xor_sync(0xffffffffu, mx, o));
        float sum = 0.f;
        for (int j = lane; j < Tz; j += 32) {
            float e = __expf(S[r * SLD + j] * inv_scale - mx);
            S[r * SLD + j] = e;
            sum += e;
        }
#pragma unroll
        for (int o = 16; o; o >>= 1) sum += __shfl_xor_sync(0xffffffffu, sum, o);
        float inv = 1.f / sum;
        for (int j = lane; j < 80; j += 32)
            P[r * PLD + j] = __float2half(j < Tz ? S[r * SLD + j] * inv : 0.f);
    }
    for (int idx = tid; idx < 9 * PLD; idx += 256)
        P[(Tz + idx / PLD) * PLD + (idx % PLD)] = __float2half(0.f);
    __syncthreads();

    FragBR bfr[5];
#pragma unroll
    for (int k = 0; k < 5; ++k)
        wmma::load_matrix_sync(bfr[k], vs + k * 16 * ALD + warp * 16, ALD);
#pragma unroll
    for (int m = 0; m < 5; ++m) {
        FragC acc;
        wmma::fill_fragment(acc, 0.f);
#pragma unroll
        for (int k = 0; k < 5; ++k) {
            FragA a;
            wmma::load_matrix_sync(a, P + m * 16 * PLD + k * 16, PLD);
            wmma::mma_sync(acc, a, bfr[k], acc);
        }
        wmma::store_matrix_sync(Ost + m * 16 * OLD + warp * 16, acc, OLD, wmma::mem_row_major);
    }
    __syncthreads();

    float*  xb  = g_x  + ((size_t)b * Tz) * Dz + h * DHz;
    __half* xhb = g_xh + ((size_t)b * Tz) * Dz + h * DHz;
    for (int idx = tid; idx < Tz * 32; idx += 256) {
        int r = idx >> 5, sg = idx & 31;
        float4 o = *(float4*)(Ost + r * OLD + sg * 4);
        float4 x = *(float4*)(xb + (size_t)r * Dz + sg * 4);
        x.x += o.x; x.y += o.y; x.z += o.z; x.w += o.w;
        *(float4*)(xb + (size_t)r * Dz + sg * 4) = x;
        __half2 h0 = __floats2half2_rn(x.x, x.y), h1 = __floats2half2_rn(x.z, x.w);
        uint2 u = make_uint2(*(uint32_t*)&h0, *(uint32_t*)&h1);
        *(uint2*)(xhb + (size_t)r * Dz + sg * 4) = u;
    }
}

// ---------------- embedding + layernorm (2 tokens per CTA) ----------------
__global__ void __launch_bounds__(256) embed_kernel(
    const int* __restrict__ fen, const int* __restrict__ move,
    const float* __restrict__ rank_emb, const float* __restrict__ file_emb,
    const float* __restrict__ fen_emb, const float* __restrict__ move_emb,
    const float* __restrict__ lng, const float* __restrict__ lnb,
    const float* __restrict__ abs_emb)
{
    __shared__ float buf[16];
    int warp = threadIdx.x >> 5, lane = threadIdx.x & 31;
    int half = warp >> 2;                    // 0/1: which token this warpgroup handles
    int token = blockIdx.x * 2 + half;
    int wtid = (warp & 3) * 32 + lane;       // 0..127 within token group
    int b = token / Tz, t = token - b * Tz;
    float vals[8];

    if (t < 64) {
        int i1 = fen[b * 133 + t];
        int i2 = fen[b * 133 + 64 + t];
        int r = t >> 3, f = t & 7;
#pragma unroll
        for (int c = 0; c < 8; ++c) {
            int d = wtid + c * 128;
            vals[c] = 0.5f * (fen_emb[i1 * Dz + d] + fen_emb[i2 * Dz + d]
                              + rank_emb[r * Dz + d] + file_emb[f * Dz + d])
                      + abs_emb[t * Dz + d];
        }
    } else if (t < 69) {
        int i1 = fen[b * 133 + 128 + (t - 64)];
#pragma unroll
        for (int c = 0; c < 8; ++c) {
            int d = wtid + c * 128;
            vals[c] = fen_emb[i1 * Dz + d] + abs_emb[t * Dz + d];
        }
    } else {
        int i = t - 69;
        int m = move[b * 2 + i];
        int r = m >> 3, f = m & 7;
#pragma unroll
        for (int c = 0; c < 8; ++c) {
            int d = wtid + c * 128;
            vals[c] = (rank_emb[r * Dz + d] + file_emb[f * Dz + d] + move_emb[i * Dz + d]) * 0.58f
                      + abs_emb[t * Dz + d];
        }
    }

    float s1 = 0.f, s2 = 0.f;
#pragma unroll
    for (int c = 0; c < 8; ++c) { s1 += vals[c]; s2 += vals[c] * vals[c]; }
#pragma unroll
    for (int o = 16; o; o >>= 1) {
        s1 += __shfl_xor_sync(0xffffffffu, s1, o);
        s2 += __shfl_xor_sync(0xffffffffu, s2, o);
    }
    if (lane == 0) { buf[warp] = s1; buf[8 + warp] = s2; }
    __syncthreads();
    float t1 = 0.f, t2 = 0.f;
#pragma unroll
    for (int w = 0; w < 4; ++w) {
        t1 += buf[half * 4 + w];
        t2 += buf[8 + half * 4 + w];
    }
    float mean = t1 * (1.f / 1024.f);
    float var  = t2 * (1.f / 1024.f) - mean * mean;
    float inv  = rsqrtf(var + 1e-5f);

    float*  xp  = g_x  + (size_t)token * Dz;
    __half* xhp = g_xh + (size_t)token * Dz;
#pragma unroll
    for (int c = 0; c < 8; ++c) {
        int d = wtid + c * 128;
        float y = (vals[c] - mean) * inv * lng[d] + lnb[d];
        xp[d]  = y;
        xhp[d] = __float2half(y);
    }
}

// ---------------- weight prep ----------------
__global__ void transposeW(const float* __restrict__ src, __half* __restrict__ dst, int K)
{
    __shared__ float tile[32][33];
    size_t mstride = (size_t)K * 128;
    src += blockIdx.z * mstride;
    dst += blockIdx.z * mstride;
    int k0 = blockIdx.x * 32, n0 = blockIdx.y * 32;
    for (int i = threadIdx.y; i < 32; i += 8)
        tile[i][threadIdx.x] = src[(size_t)(k0 + i) * 128 + n0 + threadIdx.x];
    __syncthreads();
    for (int i = threadIdx.y; i < 32; i += 8)
        dst[(size_t)(n0 + i) * K + k0 + threadIdx.x] = __float2half(tile[threadIdx.x][i]);
}

__global__ void __launch_bounds__(512) halfW1(const float* __restrict__ W1)
{
    int idx = blockIdx.x * 512 + threadIdx.x;
    g_w1h[idx] = __float2half(W1[idx]);
}

// ---------------- head: gather + LN over 2048 ----------------
__device__ __forceinline__ void blockReduce2(float& s1, float& s2) {
    __shared__ float buf[32];
    int lane = threadIdx.x & 31, warp = threadIdx.x >> 5;
#pragma unroll
    for (int o = 16; o; o >>= 1) {
        s1 += __shfl_xor_sync(0xffffffffu, s1, o);
        s2 += __shfl_xor_sync(0xffffffffu, s2, o);
    }
    if (lane == 0) { buf[warp] = s1; buf[16 + warp] = s2; }
    __syncthreads();
    float t1 = 0.f, t2 = 0.f;
#pragma unroll
    for (int w = 0; w < 8; ++w) { t1 += buf[w]; t2 += buf[16 + w]; }
    s1 = t1; s2 = t2;
}

__global__ void __launch_bounds__(256) gather_ln_kernel(const float* __restrict__ g,
                                                        const float* __restrict__ bb)
{
    int b = blockIdx.x, tid = threadIdx.x;
    const float* x69 = g_x + ((size_t)b * Tz + 69) * Dz;
    float vals[8];
#pragma unroll
    for (int c = 0; c < 8; ++c) vals[c] = x69[tid + c * 256];
    float s1 = 0.f, s2 = 0.f;
#pragma unroll
    for (int c = 0; c < 8; ++c) { s1 += vals[c]; s2 += vals[c] * vals[c]; }
    blockReduce2(s1, s2);
    float mean = s1 * (1.f / 2048.f);
    float var  = s2 * (1.f / 2048.f) - mean * mean;
    float inv  = rsqrtf(var + 1e-5f);
    __half* tp = g_th + (size_t)b * 2048;
#pragma unroll
    for (int c = 0; c < 8; ++c) {
        int k = tid + c * 256;
        tp[k] = __float2half((vals[c] - mean) * inv * g[k] + bb[k]);
    }
}

__global__ void __launch_bounds__(256) final_kernel(const float* __restrict__ W2,
                                                    const float* __restrict__ b2,
                                                    float* __restrict__ out)
{
    int b = blockIdx.x, tid = threadIdx.x;
    const float* hp = g_h1 + (size_t)b * 2048;
    float s = 0.f;
    for (int k = tid; k < 2048; k += 256) s = fmaf(hp[k], W2[k], s);
    float dummy = 0.f;
    blockReduce2(s, dummy);
    if (tid == 0) out[b] = 1.f / (1.f + __expf(-(s + b2[0])));
}

// ---------------- launch ----------------
extern "C" void kernel_launch(void* const* d_in, const int* in_sizes, int n_in,
                              void* d_out, int out_size)
{
    const int*   fen      = (const int*)  d_in[0];
    const int*   move     = (const int*)  d_in[1];
    const float* rank_emb = (const float*)d_in[2];
    const float* file_emb = (const float*)d_in[3];
    const float* fen_emb  = (const float*)d_in[4];
    const float* move_emb = (const float*)d_in[5];
    const float* ln_emb_g = (const float*)d_in[6];
    const float* ln_emb_b = (const float*)d_in[7];
    const float* abs_emb  = (const float*)d_in[8];
    const float* qkvw     = (const float*)d_in[9];
    const float* ff1w     = (const float*)d_in[10];
    const float* ff2w     = (const float*)d_in[11];
    const float* ln_out_g = (const float*)d_in[12];
    const float* ln_out_b = (const float*)d_in[13];
    const float* W1       = (const float*)d_in[14];
    const float* b1       = (const float*)d_in[15];
    const float* W2       = (const float*)d_in[16];
    const float* b2       = (const float*)d_in[17];
    float* out = (float*)d_out;

    cudaFuncSetAttribute(attn_wmma, cudaFuncAttributeMaxDynamicSharedMemorySize, ATTN_SMEM2);
    cudaFuncSetAttribute(qkv_tc,  cudaFuncAttributeMaxDynamicSharedMemorySize, GSMH);
    cudaFuncSetAttribute(ff1_tc,  cudaFuncAttributeMaxDynamicSharedMemorySize, GSMH);
    cudaFuncSetAttribute(ff2_tc,  cudaFuncAttributeMaxDynamicSharedMemorySize, GSMH);
    cudaFuncSetAttribute(head_tc, cudaFuncAttributeMaxDynamicSharedMemorySize, GSMH);

    __half* qkvT; cudaGetSymbolAddress((void**)&qkvT, g_qkvTh);
    __half* ff1T; cudaGetSymbolAddress((void**)&ff1T, g_ff1Th);
    __half* ff2T; cudaGetSymbolAddress((void**)&ff2T, g_ff2Th);
    transposeW<<<dim3(4, 4, Lz * 3 * Hz), dim3(32, 8)>>>(qkvw, qkvT, 128);
    transposeW<<<dim3(32, 4, Lz * Hz), dim3(32, 8)>>>(ff1w, ff1T, 1024);
    transposeW<<<dim3(4, 4, Lz * Hz), dim3(32, 8)>>>(ff2w, ff2T, 128);
    halfW1<<<(2 * Dz * 2 * Dz) / 512, 512>>>(W1);

    embed_kernel<<<NTOK / 2, 256>>>(fen, move, rank_emb, file_emb, fen_emb, move_emb,
                                    ln_emb_g, ln_emb_b, abs_emb);

    for (int l = 0; l < Lz; ++l) {
        const __half* qkvT_l = qkvT + (size_t)l * 3 * Hz * DHz * DHz;
        const __half* ff1T_l = ff1T + (size_t)l * Hz * DHz * Dz;
        const __half* ff2T_l = ff2T + (size_t)l * Hz * DHz * DHz;
        qkv_tc<<<dim3(24, MTILES), 256, GSMH>>>(qkvT_l);
        attn_wmma<<<dim3(Bz, Hz), 256, ATTN_SMEM2>>>();
        ff1_tc<<<dim3(8, MTILES), 256, GSMH>>>(ff1T_l);
        ff2_tc<<<dim3(8, MTILES), 256, GSMH>>>(ff2T_l);
    }

    gather_ln_kernel<<<Bz, 256>>>(ln_out_g, ln_out_b);
    head_tc<<<dim3(16, 16), 256, GSMH>>>(b1);
    final_kernel<<<Bz, 256>>>(W2, b2, out);
}

// round 17
// speedup vs baseline: 1.0042x; 1.0001x over previous
#include <cuda_runtime.h>
#include <cuda_fp16.h>
#include <mma.h>
#include <math.h>
#include <stdint.h>

using namespace nvcuda;

// ---------------- problem constants ----------------
#define Bz   2048
#define Tz   71
#define Dz   1024
#define Hz   8
#define DHz  128
#define Lz   12
#define NTOK (Bz*Tz)            // 145408
#define MTILES (NTOK/128)       // 1136

// ---------------- device scratch ----------------
__device__ float  g_x  [NTOK*Dz];   // fp32 residual stream
__device__ __half g_xh [NTOK*Dz];   // half mirror (GEMM A operand)
__device__ __half g_qh [NTOK*Dz];
__device__ __half g_kh [NTOK*Dz];
__device__ __half g_vh [NTOK*Dz];
__device__ __half g_y1h[NTOK*Dz];   // lrelu(ff1) half
__device__ __half g_th [Bz*2*Dz];
__device__ float  g_h1 [Bz*2*Dz];
__device__ __half g_qkvTh[Lz*3*Hz*DHz*DHz];
__device__ __half g_ff1Th[Lz*Hz*DHz*Dz];
__device__ __half g_ff2Th[Lz*Hz*DHz*DHz];
__device__ __half g_w1h[2*Dz*2*Dz];

__device__ __forceinline__ float lrelu(float x) { return x > 0.f ? x : 0.2f * x; }

// ---------------- cp.async helpers ----------------
__device__ __forceinline__ void cpa16(uint32_t s, const void* g) {
    asm volatile("cp.async.cg.shared.global [%0], [%1], 16;" :: "r"(s), "l"(g));
}
#define CPA_COMMIT() asm volatile("cp.async.commit_group;" ::: "memory")
#define CPA_WAIT1()  asm volatile("cp.async.wait_group 1;" ::: "memory")
#define CPA_WAIT0()  asm volatile("cp.async.wait_group 0;" ::: "memory")

// ---------------- wmma types ----------------
using FragA  = wmma::fragment<wmma::matrix_a, 16, 16, 16, __half, wmma::row_major>;
using FragB  = wmma::fragment<wmma::matrix_b, 16, 16, 16, __half, wmma::col_major>;
using FragBR = wmma::fragment<wmma::matrix_b, 16, 16, 16, __half, wmma::row_major>;
using FragC  = wmma::fragment<wmma::accumulator, 16, 16, 16, float>;

#define LDSH  72
#define MBUFH (128 * LDSH)
#define GSMH  (2 * 2 * MBUFH * 2)    // 73728 bytes: 2-stage pipeline (proven)
#define STGLD 132                    // fp32 staging stride

// A: row-major [128 x K] half, B: K-contiguous [128n x K] half => C = A @ B^T
// 2-stage cp.async double buffer (round-7 configuration).
__device__ __forceinline__ void gemm_h(const __half* __restrict__ A, int lda,
                                       const __half* __restrict__ B, int ldb,
                                       int K, FragC (&acc)[2][4], __half* sm)
{
    const int tid = threadIdx.x;
    const int warp = tid >> 5;
    const int wm = warp & 3;
    const int wn = warp >> 2;
    const uint32_t smu = (uint32_t)__cvta_generic_to_shared(sm);

#pragma unroll
    for (int i = 0; i < 2; ++i)
#pragma unroll
        for (int j = 0; j < 4; ++j)
            wmma::fill_fragment(acc[i][j], 0.f);

    const int nch = K / 64;

    auto issue = [&](int c, int buf) {
        const int kk = c * 64;
        const uint32_t base = smu + (uint32_t)buf * (2u * MBUFH * 2u);
#pragma unroll
        for (int it = 0; it < 4; ++it) {
            int idx = tid + it * 256;
            int row = idx >> 3, seg = idx & 7;
            cpa16(base + (uint32_t)(row * LDSH * 2 + seg * 16),
                  A + (size_t)row * lda + kk + seg * 8);
        }
#pragma unroll
        for (int it = 0; it < 4; ++it) {
            int idx = tid + it * 256;
            int row = idx >> 3, seg = idx & 7;
            cpa16(base + (uint32_t)(MBUFH * 2) + (uint32_t)(row * LDSH * 2 + seg * 16),
                  B + (size_t)row * ldb + kk + seg * 8);
        }
        CPA_COMMIT();
    };

    issue(0, 0);
    for (int c = 0; c < nch; ++c) {
        if (c + 1 < nch) { issue(c + 1, (c + 1) & 1); CPA_WAIT1(); }
        else             { CPA_WAIT0(); }
        __syncthreads();
        __half* As = sm + (c & 1) * 2 * MBUFH;
        __half* Bs = As + MBUFH;
#pragma unroll
        for (int ks = 0; ks < 4; ++ks) {
            FragA af[2];
            wmma::load_matrix_sync(af[0], As + (wm * 32) * LDSH + ks * 16, LDSH);
            wmma::load_matrix_sync(af[1], As + (wm * 32 + 16) * LDSH + ks * 16, LDSH);
#pragma unroll
            for (int j = 0; j < 4; ++j) {
                FragB bf;
                wmma::load_matrix_sync(bf, Bs + (wn * 64 + j * 16) * LDSH + ks * 16, LDSH);
                wmma::mma_sync(acc[0][j], af[0], bf, acc[0][j]);
                wmma::mma_sync(acc[1][j], af[1], bf, acc[1][j]);
            }
        }
        __syncthreads();
    }
}

// stage 8 acc frags to fp32 smem (stride STGLD); trailing sync
__device__ __forceinline__ void stage_acc(FragC (&acc)[2][4], float* stage) {
    int wm = (threadIdx.x >> 5) & 3, wn = threadIdx.x >> 7;
#pragma unroll
    for (int i = 0; i < 2; ++i)
#pragma unroll
        for (int j = 0; j < 4; ++j)
            wmma::store_matrix_sync(stage + (wm * 32 + i * 16) * STGLD + wn * 64 + j * 16,
                                    acc[i][j], STGLD, wmma::mem_row_major);
    __syncthreads();
}

__device__ __forceinline__ uint4 f8_to_h8(float4 a, float4 b, bool relu) {
    if (relu) {
        a.x = lrelu(a.x); a.y = lrelu(a.y); a.z = lrelu(a.z); a.w = lrelu(a.w);
        b.x = lrelu(b.x); b.y = lrelu(b.y); b.z = lrelu(b.z); b.w = lrelu(b.w);
    }
    __half2 h0 = __floats2half2_rn(a.x, a.y), h1 = __floats2half2_rn(a.z, a.w);
    __half2 h2 = __floats2half2_rn(b.x, b.y), h3 = __floats2half2_rn(b.z, b.w);
    return make_uint4(*(uint32_t*)&h0, *(uint32_t*)&h1, *(uint32_t*)&h2, *(uint32_t*)&h3);
}

// ---------------- GEMM kernels ----------------
__global__ void __launch_bounds__(256, 2) qkv_tc(const __half* __restrict__ qkvT_l)
{
    extern __shared__ __align__(128) __half smh[];
    int sh = blockIdx.x, s = sh >> 3, h = sh & 7;
    int m0 = blockIdx.y * 128;
    FragC acc[2][4];
    gemm_h(g_xh + (size_t)m0 * Dz + h * DHz, Dz,
           qkvT_l + (size_t)sh * (DHz * DHz), DHz, DHz, acc, smh);

    float* stage = (float*)smh;
    stage_acc(acc, stage);
    __half* out = (s == 0) ? g_qh : (s == 1) ? g_kh : g_vh;
#pragma unroll
    for (int it = 0; it < 8; ++it) {
        int idx = threadIdx.x + it * 256;
        int row = idx >> 4, sg = idx & 15;
        float4 a = *(float4*)(stage + row * STGLD + sg * 8);
        float4 b = *(float4*)(stage + row * STGLD + sg * 8 + 4);
        *(uint4*)(out + (size_t)(m0 + row) * Dz + h * DHz + sg * 8) = f8_to_h8(a, b, false);
    }
}

__global__ void __launch_bounds__(256, 2) ff1_tc(const __half* __restrict__ ff1T_l)
{
    extern __shared__ __align__(128) __half smh[];
    int n0 = blockIdx.x * 128, m0 = blockIdx.y * 128;
    FragC acc[2][4];
    gemm_h(g_xh + (size_t)m0 * Dz, Dz,
           ff1T_l + (size_t)n0 * Dz, Dz, Dz, acc, smh);

    float* stage = (float*)smh;
    stage_acc(acc, stage);
#pragma unroll
    for (int it = 0; it < 8; ++it) {
        int idx = threadIdx.x + it * 256;
        int row = idx >> 4, sg = idx & 15;
        float4 a = *(float4*)(stage + row * STGLD + sg * 8);
        float4 b = *(float4*)(stage + row * STGLD + sg * 8 + 4);
        *(uint4*)(g_y1h + (size_t)(m0 + row) * Dz + n0 + sg * 8) = f8_to_h8(a, b, true);
    }
}

__global__ void __launch_bounds__(256, 2) ff2_tc(const __half* __restrict__ ff2T_l)
{
    extern __shared__ __align__(128) __half smh[];
    int h = blockIdx.x, m0 = blockIdx.y * 128;
    FragC acc[2][4];
    gemm_h(g_y1h + (size_t)m0 * Dz + h * DHz, Dz,
           ff2T_l + (size_t)h * (DHz * DHz), DHz, DHz, acc, smh);

    int wm = (threadIdx.x >> 5) & 3, wn = threadIdx.x >> 7;
    float* stage = (float*)smh;
#pragma unroll
    for (int i = 0; i < 2; ++i)
#pragma unroll
        for (int j = 0; j < 4; ++j) {
            size_t off = (size_t)(m0 + wm * 32 + i * 16) * Dz + h * DHz + wn * 64 + j * 16;
            FragC c;
            wmma::load_matrix_sync(c, g_x + off, Dz, wmma::mem_row_major);
#pragma unroll
            for (int e = 0; e < c.num_elements; ++e)
                c.x[e] += lrelu(acc[i][j].x[e]);
            wmma::store_matrix_sync(g_x + off, c, Dz, wmma::mem_row_major);
            wmma::store_matrix_sync(stage + (wm * 32 + i * 16) * STGLD + wn * 64 + j * 16,
                                    c, STGLD, wmma::mem_row_major);
        }
    __syncthreads();
#pragma unroll
    for (int it = 0; it < 8; ++it) {
        int idx = threadIdx.x + it * 256;
        int row = idx >> 4, sg = idx & 15;
        float4 a = *(float4*)(stage + row * STGLD + sg * 8);
        float4 b = *(float4*)(stage + row * STGLD + sg * 8 + 4);
        *(uint4*)(g_xh + (size_t)(m0 + row) * Dz + h * DHz + sg * 8) = f8_to_h8(a, b, false);
    }
}

__global__ void __launch_bounds__(256, 2) head_tc(const float* __restrict__ b1)
{
    extern __shared__ __align__(128) __half smh[];
    int n0 = blockIdx.x * 128, m0 = blockIdx.y * 128;
    FragC acc[2][4];
    gemm_h(g_th + (size_t)m0 * 2048, 2048,
           g_w1h + (size_t)n0 * 2048, 2048, 2048, acc, smh);

    float* stage = (float*)smh;
    stage_acc(acc, stage);
#pragma unroll
    for (int it = 0; it < 16; ++it) {
        int idx = threadIdx.x + it * 256;
        int row = idx >> 5, sg = idx & 31;
        float4 a = *(float4*)(stage + row * STGLD + sg * 4);
        int col = n0 + sg * 4;
        a.x = lrelu(a.x + b1[col]);     a.y = lrelu(a.y + b1[col + 1]);
        a.z = lrelu(a.z + b1[col + 2]); a.w = lrelu(a.w + b1[col + 3]);
        *(float4*)(g_h1 + (size_t)(m0 + row) * 2048 + col) = a;
    }
}

// ---------------- attention via wmma fp16 ----------------
#define ALD 136
#define SLD 84
#define PLD 88
#define OLD 132
#define ATTN_SMEM2 (3*80*ALD*2 + 80*SLD*4 + 80*PLD*2)   // 106240

__global__ void __launch_bounds__(256, 2) attn_wmma()
{
    extern __shared__ __align__(16) char smc[];
    __half* ks = (__half*)smc;
    __half* vs = ks + 80 * ALD;
    __half* qs = vs + 80 * ALD;
    float*  S  = (float*)(qs + 80 * ALD);
    __half* P  = (__half*)(S + 80 * SLD);
    float*  Ost = (float*)(smc + 2 * 80 * ALD * 2);

    int b = blockIdx.x, h = blockIdx.y;
    int tid = threadIdx.x, warp = tid >> 5, lane = tid & 31;

    const __half* qb = g_qh + ((size_t)b * Tz) * Dz + h * DHz;
    const __half* kb = g_kh + ((size_t)b * Tz) * Dz + h * DHz;
    const __half* vb = g_vh + ((size_t)b * Tz) * Dz + h * DHz;

    for (int idx = tid; idx < Tz * 16; idx += 256) {
        int t = idx >> 4, sg = idx & 15;
        *(uint4*)(qs + t * ALD + sg * 8) = *(const uint4*)(qb + (size_t)t * Dz + sg * 8);
        *(uint4*)(ks + t * ALD + sg * 8) = *(const uint4*)(kb + (size_t)t * Dz + sg * 8);
        *(uint4*)(vs + t * ALD + sg * 8) = *(const uint4*)(vb + (size_t)t * Dz + sg * 8);
    }
    // Only V pad rows must be zero (P pad cols are 0; 0*NaN would poison O).
    // q/k pad rows feed S rows/cols >= 71 which are never read.
    uint4 z4 = make_uint4(0, 0, 0, 0);
    for (int idx = tid; idx < 9 * 16; idx += 256) {
        int t = 71 + (idx >> 4), sg = idx & 15;
        *(uint4*)(vs + t * ALD + sg * 8) = z4;
    }
    __syncthreads();

    for (int t = warp; t < 25; t += 8) {
        int mi = t / 5, nj = t % 5;
        FragC acc;
        wmma::fill_fragment(acc, 0.f);
#pragma unroll
        for (int k = 0; k < 8; ++k) {
            FragA a; FragB bf;
            wmma::load_matrix_sync(a,  qs + mi * 16 * ALD + k * 16, ALD);
            wmma::load_matrix_sync(bf, ks + nj * 16 * ALD + k * 16, ALD);
            wmma::mma_sync(acc, a, bf, acc);
        }
        wmma::store_matrix_sync(S + mi * 16 * SLD + nj * 16, acc, SLD, wmma::mem_row_major);
    }
    __syncthreads();

    const float inv_scale = 0.08838834764831845f;
    for (int r = warp; r < Tz; r += 8) {
        float mx = -1e30f;
        for (int j = lane; j < Tz; j += 32) mx = fmaxf(mx, S[r * SLD + j] * inv_scale);
#pragma unroll
        for (int o = 16; o; o >>= 1) mx = fmaxf(mx, __shfl_xor_sync(0xffffffffu, mx, o));
        float sum = 0.f;
        for (int j = lane; j < Tz; j += 32) {
            float e = __expf(S[r * SLD + j] * inv_scale - mx);
            S[r * SLD + j] = e;
            sum += e;
        }
#pragma unroll
        for (int o = 16; o; o >>= 1) sum += __shfl_xor_sync(0xffffffffu, sum, o);
        float inv = 1.f / sum;
        for (int j = lane; j < 80; j += 32)
            P[r * PLD + j] = __float2half(j < Tz ? S[r * SLD + j] * inv : 0.f);
    }
    for (int idx = tid; idx < 9 * PLD; idx += 256)
        P[(Tz + idx / PLD) * PLD + (idx % PLD)] = __float2half(0.f);
    __syncthreads();

    FragBR bfr[5];
#pragma unroll
    for (int k = 0; k < 5; ++k)
        wmma::load_matrix_sync(bfr[k], vs + k * 16 * ALD + warp * 16, ALD);
#pragma unroll
    for (int m = 0; m < 5; ++m) {
        FragC acc;
        wmma::fill_fragment(acc, 0.f);
#pragma unroll
        for (int k = 0; k < 5; ++k) {
            FragA a;
            wmma::load_matrix_sync(a, P + m * 16 * PLD + k * 16, PLD);
            wmma::mma_sync(acc, a, bfr[k], acc);
        }
        wmma::store_matrix_sync(Ost + m * 16 * OLD + warp * 16, acc, OLD, wmma::mem_row_major);
    }
    __syncthreads();

    float*  xb  = g_x  + ((size_t)b * Tz) * Dz + h * DHz;
    __half* xhb = g_xh + ((size_t)b * Tz) * Dz + h * DHz;
    for (int idx = tid; idx < Tz * 32; idx += 256) {
        int r = idx >> 5, sg = idx & 31;
        float4 o = *(float4*)(Ost + r * OLD + sg * 4);
        float4 x = *(float4*)(xb + (size_t)r * Dz + sg * 4);
        x.x += o.x; x.y += o.y; x.z += o.z; x.w += o.w;
        *(float4*)(xb + (size_t)r * Dz + sg * 4) = x;
        __half2 h0 = __floats2half2_rn(x.x, x.y), h1 = __floats2half2_rn(x.z, x.w);
        uint2 u = make_uint2(*(uint32_t*)&h0, *(uint32_t*)&h1);
        *(uint2*)(xhb + (size_t)r * Dz + sg * 4) = u;
    }
}

// ---------------- embedding + layernorm (2 tokens per CTA) ----------------
__global__ void __launch_bounds__(256) embed_kernel(
    const int* __restrict__ fen, const int* __restrict__ move,
    const float* __restrict__ rank_emb, const float* __restrict__ file_emb,
    const float* __restrict__ fen_emb, const float* __restrict__ move_emb,
    const float* __restrict__ lng, const float* __restrict__ lnb,
    const float* __restrict__ abs_emb)
{
    __shared__ float buf[16];
    int warp = threadIdx.x >> 5, lane = threadIdx.x & 31;
    int half = warp >> 2;                    // 0/1: which token this warpgroup handles
    int token = blockIdx.x * 2 + half;
    int wtid = (warp & 3) * 32 + lane;       // 0..127 within token group
    int b = token / Tz, t = token - b * Tz;
    float vals[8];

    if (t < 64) {
        int i1 = fen[b * 133 + t];
        int i2 = fen[b * 133 + 64 + t];
        int r = t >> 3, f = t & 7;
#pragma unroll
        for (int c = 0; c < 8; ++c) {
            int d = wtid + c * 128;
            vals[c] = 0.5f * (fen_emb[i1 * Dz + d] + fen_emb[i2 * Dz + d]
                              + rank_emb[r * Dz + d] + file_emb[f * Dz + d])
                      + abs_emb[t * Dz + d];
        }
    } else if (t < 69) {
        int i1 = fen[b * 133 + 128 + (t - 64)];
#pragma unroll
        for (int c = 0; c < 8; ++c) {
            int d = wtid + c * 128;
            vals[c] = fen_emb[i1 * Dz + d] + abs_emb[t * Dz + d];
        }
    } else {
        int i = t - 69;
        int m = move[b * 2 + i];
        int r = m >> 3, f = m & 7;
#pragma unroll
        for (int c = 0; c < 8; ++c) {
            int d = wtid + c * 128;
            vals[c] = (rank_emb[r * Dz + d] + file_emb[f * Dz + d] + move_emb[i * Dz + d]) * 0.58f
                      + abs_emb[t * Dz + d];
        }
    }

    float s1 = 0.f, s2 = 0.f;
#pragma unroll
    for (int c = 0; c < 8; ++c) { s1 += vals[c]; s2 += vals[c] * vals[c]; }
#pragma unroll
    for (int o = 16; o; o >>= 1) {
        s1 += __shfl_xor_sync(0xffffffffu, s1, o);
        s2 += __shfl_xor_sync(0xffffffffu, s2, o);
    }
    if (lane == 0) { buf[warp] = s1; buf[8 + warp] = s2; }
    __syncthreads();
    float t1 = 0.f, t2 = 0.f;
#pragma unroll
    for (int w = 0; w < 4; ++w) {
        t1 += buf[half * 4 + w];
        t2 += buf[8 + half * 4 + w];
    }
    float mean = t1 * (1.f / 1024.f);
    float var  = t2 * (1.f / 1024.f) - mean * mean;
    float inv  = rsqrtf(var + 1e-5f);

    float*  xp  = g_x  + (size_t)token * Dz;
    __half* xhp = g_xh + (size_t)token * Dz;
#pragma unroll
    for (int c = 0; c < 8; ++c) {
        int d = wtid + c * 128;
        float y = (vals[c] - mean) * inv * lng[d] + lnb[d];
        xp[d]  = y;
        xhp[d] = __float2half(y);
    }
}

// ---------------- weight prep ----------------
__global__ void transposeW(const float* __restrict__ src, __half* __restrict__ dst, int K)
{
    __shared__ float tile[32][33];
    size_t mstride = (size_t)K * 128;
    src += blockIdx.z * mstride;
    dst += blockIdx.z * mstride;
    int k0 = blockIdx.x * 32, n0 = blockIdx.y * 32;
    for (int i = threadIdx.y; i < 32; i += 8)
        tile[i][threadIdx.x] = src[(size_t)(k0 + i) * 128 + n0 + threadIdx.x];
    __syncthreads();
    for (int i = threadIdx.y; i < 32; i += 8)
        dst[(size_t)(n0 + i) * K + k0 + threadIdx.x] = __float2half(tile[threadIdx.x][i]);
}

__global__ void __launch_bounds__(512) halfW1(const float* __restrict__ W1)
{
    int idx = blockIdx.x * 512 + threadIdx.x;
    g_w1h[idx] = __float2half(W1[idx]);
}

// ---------------- head: gather + LN over 2048 ----------------
__device__ __forceinline__ void blockReduce2(float& s1, float& s2) {
    __shared__ float buf[32];
    int lane = threadIdx.x & 31, warp = threadIdx.x >> 5;
#pragma unroll
    for (int o = 16; o; o >>= 1) {
        s1 += __shfl_xor_sync(0xffffffffu, s1, o);
        s2 += __shfl_xor_sync(0xffffffffu, s2, o);
    }
    if (lane == 0) { buf[warp] = s1; buf[16 + warp] = s2; }
    __syncthreads();
    float t1 = 0.f, t2 = 0.f;
#pragma unroll
    for (int w = 0; w < 8; ++w) { t1 += buf[w]; t2 += buf[16 + w]; }
    s1 = t1; s2 = t2;
}

__global__ void __launch_bounds__(256) gather_ln_kernel(const float* __restrict__ g,
                                                        const float* __restrict__ bb)
{
    int b = blockIdx.x, tid = threadIdx.x;
    const float* x69 = g_x + ((size_t)b * Tz + 69) * Dz;
    float vals[8];
#pragma unroll
    for (int c = 0; c < 8; ++c) vals[c] = x69[tid + c * 256];
    float s1 = 0.f, s2 = 0.f;
#pragma unroll
    for (int c = 0; c < 8; ++c) { s1 += vals[c]; s2 += vals[c] * vals[c]; }
    blockReduce2(s1, s2);
    float mean = s1 * (1.f / 2048.f);
    float var  = s2 * (1.f / 2048.f) - mean * mean;
    float inv  = rsqrtf(var + 1e-5f);
    __half* tp = g_th + (size_t)b * 2048;
#pragma unroll
    for (int c = 0; c < 8; ++c) {
        int k = tid + c * 256;
        tp[k] = __float2half((vals[c] - mean) * inv * g[k] + bb[k]);
    }
}

__global__ void __launch_bounds__(256) final_kernel(const float* __restrict__ W2,
                                                    const float* __restrict__ b2,
                                                    float* __restrict__ out)
{
    int b = blockIdx.x, tid = threadIdx.x;
    const float* hp = g_h1 + (size_t)b * 2048;
    float s = 0.f;
    for (int k = tid; k < 2048; k += 256) s = fmaf(hp[k], W2[k], s);
    float dummy = 0.f;
    blockReduce2(s, dummy);
    if (tid == 0) out[b] = 1.f / (1.f + __expf(-(s + b2[0])));
}

// ---------------- launch ----------------
extern "C" void kernel_launch(void* const* d_in, const int* in_sizes, int n_in,
                              void* d_out, int out_size)
{
    const int*   fen      = (const int*)  d_in[0];
    const int*   move     = (const int*)  d_in[1];
    const float* rank_emb = (const float*)d_in[2];
    const float* file_emb = (const float*)d_in[3];
    const float* fen_emb  = (const float*)d_in[4];
    const float* move_emb = (const float*)d_in[5];
    const float* ln_emb_g = (const float*)d_in[6];
    const float* ln_emb_b = (const float*)d_in[7];
    const float* abs_emb  = (const float*)d_in[8];
    const float* qkvw     = (const float*)d_in[9];
    const float* ff1w     = (const float*)d_in[10];
    const float* ff2w     = (const float*)d_in[11];
    const float* ln_out_g = (const float*)d_in[12];
    const float* ln_out_b = (const float*)d_in[13];
    const float* W1       = (const float*)d_in[14];
    const float* b1       = (const float*)d_in[15];
    const float* W2       = (const float*)d_in[16];
    const float* b2       = (const float*)d_in[17];
    float* out = (float*)d_out;

    cudaFuncSetAttribute(attn_wmma, cudaFuncAttributeMaxDynamicSharedMemorySize, ATTN_SMEM2);
    cudaFuncSetAttribute(qkv_tc,  cudaFuncAttributeMaxDynamicSharedMemorySize, GSMH);
    cudaFuncSetAttribute(ff1_tc,  cudaFuncAttributeMaxDynamicSharedMemorySize, GSMH);
    cudaFuncSetAttribute(ff2_tc,  cudaFuncAttributeMaxDynamicSharedMemorySize, GSMH);
    cudaFuncSetAttribute(head_tc, cudaFuncAttributeMaxDynamicSharedMemorySize, GSMH);

    __half* qkvT; cudaGetSymbolAddress((void**)&qkvT, g_qkvTh);
    __half* ff1T; cudaGetSymbolAddress((void**)&ff1T, g_ff1Th);
    __half* ff2T; cudaGetSymbolAddress((void**)&ff2T, g_ff2Th);
    transposeW<<<dim3(4, 4, Lz * 3 * Hz), dim3(32, 8)>>>(qkvw, qkvT, 128);
    transposeW<<<dim3(32, 4, Lz * Hz), dim3(32, 8)>>>(ff1w, ff1T, 1024);
    transposeW<<<dim3(4, 4, Lz * Hz), dim3(32, 8)>>>(ff2w, ff2T, 128);
    halfW1<<<(2 * Dz * 2 * Dz) / 512, 512>>>(W1);

    embed_kernel<<<NTOK / 2, 256>>>(fen, move, rank_emb, file_emb, fen_emb, move_emb,
                                    ln_emb_g, ln_emb_b, abs_emb);

    for (int l = 0; l < Lz; ++l) {
        const __half* qkvT_l = qkvT + (size_t)l * 3 * Hz * DHz * DHz;
        const __half* ff1T_l = ff1T + (size_t)l * Hz * DHz * Dz;
        const __half* ff2T_l = ff2T + (size_t)l * Hz * DHz * DHz;
        qkv_tc<<<dim3(24, MTILES), 256, GSMH>>>(qkvT_l);
        attn_wmma<<<dim3(Bz, Hz), 256, ATTN_SMEM2>>>();
        ff1_tc<<<dim3(8, MTILES), 256, GSMH>>>(ff1T_l);
        ff2_tc<<<dim3(8, MTILES), 256, GSMH>>>(ff2T_l);
    }

    gather_ln_kernel<<<Bz, 256>>>(ln_out_g, ln_out_b);
    head_tc<<<dim3(16, 16), 256, GSMH>>>(b1);
    final_kernel<<<Bz, 256>>>(W2, b2, out);
}